// round 15
// baseline (speedup 1.0000x reference)
#include <cuda_runtime.h>
#include <cuda_bf16.h>
#include <cuda_fp16.h>
#include <math.h>
#include <cstdint>

// Problem constants
#define Bb   8
#define Ss   1024
#define Dd   1024
#define Hh   16
#define HD   64
#define Nn   16
#define TOK  (Bb*Ss)              // 8192
#define ELEM ((size_t)Bb*Ss*Dd)   // 8388608

// Scratch (allocation-free rule: device globals)
__device__ float  g_q[ELEM];                 // fp32 q (ded_proj target; unused downstream)
__device__ __half g_xh[ELEM];                // fp16 x
__device__ __half g_wth[4 * Dd * Dd];        // fp16 transposed Wq,Wk,Wv,Wo
__device__ __half g_ah[ELEM];                // fp16 attention output
__device__ __half g_qh[ELEM];                // fp16 q
__device__ __half g_kh[ELEM];                // fp16 k
__device__ __half g_vh[ELEM];                // fp16 v

__device__ __forceinline__ uint32_t pack_half2(float a, float b) {
    uint32_t r;
    asm("cvt.rn.f16x2.f32 %0, %2, %1;" : "=r"(r) : "f"(a), "f"(b));
    return r;   // low half = a, high half = b
}

// ---------------------------------------------------------------------------
// Elementwise fp32 -> fp16 (x -> xh)
// ---------------------------------------------------------------------------
__global__ __launch_bounds__(256) void cvt_half_kernel(
    const float* __restrict__ in, __half* __restrict__ out, int n4)
{
    int i = blockIdx.x * blockDim.x + threadIdx.x;
    int stride = gridDim.x * blockDim.x;
    for (; i < n4; i += stride) {
        float4 v = ((const float4*)in)[i];
        ((__half2*)out)[2 * i]     = __floats2half2_rn(v.x, v.y);
        ((__half2*)out)[2 * i + 1] = __floats2half2_rn(v.z, v.w);
    }
}

// ---------------------------------------------------------------------------
// Batched W transpose + fp16 convert: out[z][n][k] = half(in[z][k][n])
// ---------------------------------------------------------------------------
__global__ __launch_bounds__(256) void transpose_h4_kernel(
    const float* __restrict__ in0, const float* __restrict__ in1,
    const float* __restrict__ in2, const float* __restrict__ in3,
    __half* __restrict__ out)
{
    __shared__ float t[32][33];
    const float* in = (blockIdx.z == 0) ? in0 : (blockIdx.z == 1 ? in1 :
                      (blockIdx.z == 2) ? in2 : in3);
    __half* dst = out + (size_t)blockIdx.z * Dd * Dd;

    int x = blockIdx.x * 32 + threadIdx.x;
    int y = blockIdx.y * 32 + threadIdx.y;
#pragma unroll
    for (int j = 0; j < 32; j += 8)
        t[threadIdx.y + j][threadIdx.x] = in[(size_t)(y + j) * Dd + x];
    __syncthreads();
    x = blockIdx.y * 32 + threadIdx.x;
    y = blockIdx.x * 32 + threadIdx.y;
#pragma unroll
    for (int j = 0; j < 32; j += 8)
        dst[(size_t)(y + j) * Dd + x] = __float2half_rn(t[threadIdx.x][threadIdx.y + j]);
}

// ---------------------------------------------------------------------------
// fp16 tensor-core GEMM: C[M,Nc] = A[M,K] @ Wt[Nc,K]^T, fp32 accumulate.
// CTA tile 128x128, GBK=64, 256 threads (8 warps, 4m x 2n, warp 32x64),
// NSTAGE=3, ~110KB smem -> 2 CTAs/SM. (unchanged from R14)
// ---------------------------------------------------------------------------
#define GBM 128
#define GBN 128
#define GBK 64
#define ASTR 72
#define NSTAGE 3
#define GEMM_SMEM (NSTAGE * (GBM + GBN) * ASTR * 2)   // 110592 B

__global__ void __launch_bounds__(256, 2)
h_gemm_kernel(const __half* __restrict__ A,
              const __half* __restrict__ Wt0, const __half* __restrict__ Wt1,
              const __half* __restrict__ Wt2,
              float* __restrict__ C0, float* __restrict__ C1,
              float* __restrict__ C2,
              __half* __restrict__ H0, __half* __restrict__ H1,
              __half* __restrict__ H2, int K)
{
    extern __shared__ __half smemh[];
    __half* As = smemh;
    __half* Bs = smemh + NSTAGE * GBM * ASTR;

    const __half* Wt = (blockIdx.z == 0) ? Wt0 : (blockIdx.z == 1 ? Wt1 : Wt2);
    float* C         = (blockIdx.z == 0) ? C0  : (blockIdx.z == 1 ? C1  : C2);
    __half* Hc       = (blockIdx.z == 0) ? H0  : (blockIdx.z == 1 ? H1  : H2);

    const int tid  = threadIdx.x;
    const int lane = tid & 31;
    const int wid  = tid >> 5;
    const int wm   = (wid & 3) * 32;
    const int wn   = (wid >> 2) * 64;
    const int m0   = blockIdx.y * GBM;
    const int n0   = blockIdx.x * GBN;

    const uint32_t sA = (uint32_t)__cvta_generic_to_shared(As);
    const uint32_t sB = (uint32_t)__cvta_generic_to_shared(Bs);

    float acc[2][8][4];
#pragma unroll
    for (int mf = 0; mf < 2; mf++)
#pragma unroll
        for (int nf = 0; nf < 8; nf++)
#pragma unroll
            for (int r = 0; r < 4; r++) acc[mf][nf][r] = 0.f;

    const __half* Abase = A + (size_t)m0 * K;
    const __half* Bbase = Wt + (size_t)n0 * K;

    auto load_tile = [&](int k0, int st) {
        uint32_t dstA = sA + (uint32_t)st * (GBM * ASTR * 2);
#pragma unroll
        for (int j = 0; j < 4; j++) {
            int g = tid + 256 * j;
            int m = g >> 3, c = g & 7;
            const __half* src = Abase + (size_t)m * K + k0 + c * 8;
            asm volatile("cp.async.ca.shared.global [%0], [%1], 16;\n"
                         :: "r"(dstA + (uint32_t)(m * ASTR + c * 8) * 2), "l"(src));
        }
        uint32_t dstB = sB + (uint32_t)st * (GBN * ASTR * 2);
#pragma unroll
        for (int j = 0; j < 4; j++) {
            int g = tid + 256 * j;
            int n = g >> 3, c = g & 7;
            const __half* src = Bbase + (size_t)n * K + k0 + c * 8;
            asm volatile("cp.async.ca.shared.global [%0], [%1], 16;\n"
                         :: "r"(dstB + (uint32_t)(n * ASTR + c * 8) * 2), "l"(src));
        }
    };

    const int ql = lane >> 3, rl = lane & 7;

    auto compute = [&](int st) {
        const uint32_t baseA = sA + (uint32_t)st * (GBM * ASTR * 2);
        const uint32_t baseB = sB + (uint32_t)st * (GBN * ASTR * 2);
#pragma unroll
        for (int t = 0; t < 4; t++) {
            uint32_t a[2][4];
#pragma unroll
            for (int mf = 0; mf < 2; mf++) {
                int mrow = wm + mf * 16 + rl + (ql & 1) * 8;
                int kc   = t * 16 + (ql >> 1) * 8;
                uint32_t addr = baseA + (uint32_t)(mrow * ASTR + kc) * 2;
                asm volatile(
                    "ldmatrix.sync.aligned.m8n8.x4.shared.b16 {%0,%1,%2,%3}, [%4];"
                    : "=r"(a[mf][0]), "=r"(a[mf][1]), "=r"(a[mf][2]), "=r"(a[mf][3])
                    : "r"(addr));
            }
            uint32_t b[4][4];
#pragma unroll
            for (int p = 0; p < 4; p++) {
                int nrow = wn + (2 * p + (ql >> 1)) * 8 + rl;
                int kc   = t * 16 + (ql & 1) * 8;
                uint32_t addr = baseB + (uint32_t)(nrow * ASTR + kc) * 2;
                asm volatile(
                    "ldmatrix.sync.aligned.m8n8.x4.shared.b16 {%0,%1,%2,%3}, [%4];"
                    : "=r"(b[p][0]), "=r"(b[p][1]), "=r"(b[p][2]), "=r"(b[p][3])
                    : "r"(addr));
            }
#pragma unroll
            for (int mf = 0; mf < 2; mf++)
#pragma unroll
                for (int nf = 0; nf < 8; nf++) {
                    uint32_t b0 = b[nf >> 1][(nf & 1) * 2];
                    uint32_t b1 = b[nf >> 1][(nf & 1) * 2 + 1];
                    asm volatile(
                        "mma.sync.aligned.m16n8k16.row.col.f32.f16.f16.f32 "
                        "{%0,%1,%2,%3}, {%4,%5,%6,%7}, {%8,%9}, {%0,%1,%2,%3};"
                        : "+f"(acc[mf][nf][0]), "+f"(acc[mf][nf][1]),
                          "+f"(acc[mf][nf][2]), "+f"(acc[mf][nf][3])
                        : "r"(a[mf][0]), "r"(a[mf][1]), "r"(a[mf][2]), "r"(a[mf][3]),
                          "r"(b0), "r"(b1));
                }
        }
    };

    load_tile(0, 0);
    asm volatile("cp.async.commit_group;");
    load_tile(GBK, 1);
    asm volatile("cp.async.commit_group;");

    const int niter = K / GBK;
    for (int i = 0; i < niter; i++) {
        asm volatile("cp.async.wait_group 1;");
        __syncthreads();
        if ((i + 2) * GBK < K)
            load_tile((i + 2) * GBK, (i + 2) % NSTAGE);
        asm volatile("cp.async.commit_group;");
        compute(i % NSTAGE);
    }

#pragma unroll
    for (int mf = 0; mf < 2; mf++) {
        int row = m0 + wm + mf * 16 + (lane >> 2);
#pragma unroll
        for (int nf = 0; nf < 8; nf++) {
            int col = n0 + wn + nf * 8 + (lane & 3) * 2;
            if (C) {
                *(float2*)&C[(size_t)row * Dd + col] =
                    make_float2(acc[mf][nf][0], acc[mf][nf][1]);
                *(float2*)&C[(size_t)(row + 8) * Dd + col] =
                    make_float2(acc[mf][nf][2], acc[mf][nf][3]);
            }
            if (Hc) {
                *(uint32_t*)&Hc[(size_t)row * Dd + col] =
                    pack_half2(acc[mf][nf][0], acc[mf][nf][1]);
                *(uint32_t*)&Hc[(size_t)(row + 8) * Dd + col] =
                    pack_half2(acc[mf][nf][2], acc[mf][nf][3]);
            }
        }
    }
}

// ---------------------------------------------------------------------------
// Dedicated projection (fused q/k/v), fp32 compute; dual fp32+fp16 writes.
// Re-partitioned for occupancy: o-tile 32, 32 k-chunks of 32, grid 1536.
// ---------------------------------------------------------------------------
__global__ __launch_bounds__(256) void ded_proj_kernel(
    const float* __restrict__ x,
    const float* __restrict__ Wq_ded, const float* __restrict__ Wk_ded,
    const float* __restrict__ Wv_ded,
    float* __restrict__ qb, float* __restrict__ kb, float* __restrict__ vb,
    __half* __restrict__ qh, __half* __restrict__ kh, __half* __restrict__ vh)
{
    __shared__ float sm[8192];
    const int n   = blockIdx.y;
    const int o0  = blockIdx.x * 32;
    const int tid = threadIdx.x;
    const float* Wd = (blockIdx.z == 0) ? Wq_ded : (blockIdx.z == 1 ? Wk_ded : Wv_ded);
    float* out      = (blockIdx.z == 0) ? qb     : (blockIdx.z == 1 ? kb     : vb);
    __half* outh    = (blockIdx.z == 0) ? qh     : (blockIdx.z == 1 ? kh     : vh);

    for (int i = tid; i < Bb * Dd; i += 256) {
        int b = i >> 10, k = i & 1023;
        sm[i] = x[((size_t)b * Ss + n) * Dd + k];
    }
    __syncthreads();

    const int of4 = tid & 7;     // 8 float4 -> 32 o
    const int ks  = tid >> 3;    // 32 k-chunks of 32
    const float* Wp = Wd + (size_t)n * Dd * Dd + (size_t)(ks * 32) * Dd + o0 + of4 * 4;

    float acc[8][4];
#pragma unroll
    for (int b = 0; b < 8; b++)
#pragma unroll
        for (int j = 0; j < 4; j++) acc[b][j] = 0.f;

#pragma unroll 8
    for (int kk = 0; kk < 32; kk++) {
        float4 w = *(const float4*)(Wp + (size_t)kk * Dd);
        int k = ks * 32 + kk;
#pragma unroll
        for (int b = 0; b < 8; b++) {
            float xv = sm[b * 1024 + k];
            acc[b][0] += xv * w.x; acc[b][1] += xv * w.y;
            acc[b][2] += xv * w.z; acc[b][3] += xv * w.w;
        }
    }
    __syncthreads();   // done reading xs; reuse smem for partials

#pragma unroll
    for (int b = 0; b < 8; b++)
        *(float4*)&sm[ks * 256 + b * 32 + of4 * 4] =
            make_float4(acc[b][0], acc[b][1], acc[b][2], acc[b][3]);
    __syncthreads();

    {   // exactly one output element per thread: 8 batches x 32 o = 256
        int b = tid >> 5, ol = tid & 31;
        float s = 0.f;
#pragma unroll
        for (int k2 = 0; k2 < 32; k2++) s += sm[k2 * 256 + tid];
        size_t idx = ((size_t)b * Ss + n) * Dd + o0 + ol;
        out[idx]  = s;
        outh[idx] = __float2half_rn(s);
    }
}

// ---------------------------------------------------------------------------
// Tensor-core causal flash attention — fully fp16 operands, fp32 softmax/acc.
// Heavy blocks (large q0) launch first to trim the tail wave.
// ---------------------------------------------------------------------------
#define ABQ 128
#define ABK 64
#define KHSTR 72
#define VSTR  72
#define ATTN_SMEM (2*ABK*KHSTR*2 + 2*ABK*VSTR*2)   // 36864 B

__global__ __launch_bounds__(256) void attn_tc_kernel(
    const __half* __restrict__ Qh, const __half* __restrict__ Kh,
    const __half* __restrict__ Vh, __half* __restrict__ OH)
{
    extern __shared__ char asmem[];
    __half* Ks = (__half*)asmem;
    __half* Vs = (__half*)(asmem + 2 * ABK * KHSTR * 2);

    const int b   = blockIdx.z;
    const int h   = blockIdx.y;
    const int q0  = ((int)gridDim.x - 1 - (int)blockIdx.x) * ABQ;  // heavy first
    const int tid = threadIdx.x;
    const int lane = tid & 31;
    const int wid  = tid >> 5;
    const int wq0  = q0 + wid * 16;
    const int r = lane >> 2;
    const int c = lane & 3;

    const uint32_t sKs = (uint32_t)__cvta_generic_to_shared(Ks);
    const uint32_t sVs = (uint32_t)__cvta_generic_to_shared(Vs);

    uint32_t qf[4][4];
    {
        const __half* q0p = Qh + ((size_t)(b * Ss) + wq0 + r) * Dd + h * HD;
        const __half* q1p = q0p + 8 * (size_t)Dd;
#pragma unroll
        for (int t = 0; t < 4; t++) {
            qf[t][0] = *(const uint32_t*)&q0p[t * 16 + 2 * c];
            qf[t][1] = *(const uint32_t*)&q1p[t * 16 + 2 * c];
            qf[t][2] = *(const uint32_t*)&q0p[t * 16 + 2 * c + 8];
            qf[t][3] = *(const uint32_t*)&q1p[t * 16 + 2 * c + 8];
        }
    }

    const __half* Kbase = Kh + (size_t)(b * Ss) * Dd + h * HD;
    const __half* Vbase = Vh + (size_t)(b * Ss) * Dd + h * HD;

    auto load_k = [&](int k0, int buf) {
        uint32_t dst = sKs + (uint32_t)buf * (ABK * KHSTR * 2);
#pragma unroll
        for (int j = 0; j < 2; j++) {
            int g = tid + 256 * j;
            int row = g >> 3, c8 = g & 7;
            const __half* src = Kbase + (size_t)(k0 + row) * Dd + c8 * 8;
            asm volatile("cp.async.ca.shared.global [%0], [%1], 16;\n"
                         :: "r"(dst + (uint32_t)(row * KHSTR + c8 * 8) * 2), "l"(src));
        }
    };
    auto load_v = [&](int k0, int buf) {
        uint32_t dst = sVs + (uint32_t)buf * (ABK * VSTR * 2);
#pragma unroll
        for (int j = 0; j < 2; j++) {
            int g = tid + 256 * j;
            int row = g >> 3, c8 = g & 7;
            const __half* src = Vbase + (size_t)(k0 + row) * Dd + c8 * 8;
            asm volatile("cp.async.ca.shared.global [%0], [%1], 16;\n"
                         :: "r"(dst + (uint32_t)(row * VSTR + c8 * 8) * 2), "l"(src));
        }
    };

    float o[8][4];
#pragma unroll
    for (int j = 0; j < 8; j++)
#pragma unroll
        for (int e = 0; e < 4; e++) o[j][e] = 0.f;
    float m0 = -1e30f, m1 = -1e30f, l0 = 0.f, l1 = 0.f;

    const int kend = q0 + ABQ;
    load_k(0, 0);
    load_v(0, 0);
    asm volatile("cp.async.commit_group;");

    int buf = 0;
    const int ql = lane >> 3, rl = lane & 7;

    for (int k0 = 0; k0 < kend; k0 += ABK) {
        asm volatile("cp.async.wait_group 0;");
        __syncthreads();
        if (k0 + ABK < kend) {
            load_k(k0 + ABK, buf ^ 1);
            load_v(k0 + ABK, buf ^ 1);
            asm volatile("cp.async.commit_group;");
        }

        if (k0 <= wq0 + 15) {
            float s[8][4];
#pragma unroll
            for (int j = 0; j < 8; j++)
#pragma unroll
                for (int e = 0; e < 4; e++) s[j][e] = 0.f;

            const uint32_t baseK = sKs + (uint32_t)buf * (ABK * KHSTR * 2);
#pragma unroll
            for (int t = 0; t < 4; t++) {
                uint32_t bk[4][4];
#pragma unroll
                for (int p = 0; p < 4; p++) {
                    int nrow = (2 * p + (ql >> 1)) * 8 + rl;
                    int kc   = t * 16 + (ql & 1) * 8;
                    uint32_t addr = baseK + (uint32_t)(nrow * KHSTR + kc) * 2;
                    asm volatile(
                        "ldmatrix.sync.aligned.m8n8.x4.shared.b16 {%0,%1,%2,%3}, [%4];"
                        : "=r"(bk[p][0]), "=r"(bk[p][1]), "=r"(bk[p][2]), "=r"(bk[p][3])
                        : "r"(addr));
                }
#pragma unroll
                for (int j = 0; j < 8; j++) {
                    uint32_t b0 = bk[j >> 1][(j & 1) * 2];
                    uint32_t b1 = bk[j >> 1][(j & 1) * 2 + 1];
                    asm volatile(
                        "mma.sync.aligned.m16n8k16.row.col.f32.f16.f16.f32 "
                        "{%0,%1,%2,%3}, {%4,%5,%6,%7}, {%8,%9}, {%0,%1,%2,%3};"
                        : "+f"(s[j][0]), "+f"(s[j][1]), "+f"(s[j][2]), "+f"(s[j][3])
                        : "r"(qf[t][0]), "r"(qf[t][1]), "r"(qf[t][2]), "r"(qf[t][3]),
                          "r"(b0), "r"(b1));
                }
            }

            const bool need_mask = (k0 + 63 > wq0);
            float rmax0 = -1e30f, rmax1 = -1e30f;
#pragma unroll
            for (int j = 0; j < 8; j++) {
#pragma unroll
                for (int e = 0; e < 2; e++) {
                    float v0 = s[j][e]     * 0.125f;
                    float v1 = s[j][2 + e] * 0.125f;
                    if (need_mask) {
                        int col = k0 + j * 8 + 2 * c + e;
                        if (col > wq0 + r)     v0 = -1e30f;
                        if (col > wq0 + r + 8) v1 = -1e30f;
                    }
                    s[j][e] = v0; s[j][2 + e] = v1;
                    rmax0 = fmaxf(rmax0, v0);
                    rmax1 = fmaxf(rmax1, v1);
                }
            }
            rmax0 = fmaxf(rmax0, __shfl_xor_sync(0xffffffffu, rmax0, 1));
            rmax0 = fmaxf(rmax0, __shfl_xor_sync(0xffffffffu, rmax0, 2));
            rmax1 = fmaxf(rmax1, __shfl_xor_sync(0xffffffffu, rmax1, 1));
            rmax1 = fmaxf(rmax1, __shfl_xor_sync(0xffffffffu, rmax1, 2));

            float mn0 = fmaxf(m0, rmax0), mn1 = fmaxf(m1, rmax1);
            float corr0 = __expf(m0 - mn0), corr1 = __expf(m1 - mn1);
            m0 = mn0; m1 = mn1;

            float ls0 = 0.f, ls1 = 0.f;
#pragma unroll
            for (int j = 0; j < 8; j++) {
                s[j][0] = __expf(s[j][0] - mn0);
                s[j][1] = __expf(s[j][1] - mn0);
                s[j][2] = __expf(s[j][2] - mn1);
                s[j][3] = __expf(s[j][3] - mn1);
                ls0 += s[j][0] + s[j][1];
                ls1 += s[j][2] + s[j][3];
            }
            l0 = l0 * corr0 + ls0;
            l1 = l1 * corr1 + ls1;
#pragma unroll
            for (int j = 0; j < 8; j++) {
                o[j][0] *= corr0; o[j][1] *= corr0;
                o[j][2] *= corr1; o[j][3] *= corr1;
            }

#pragma unroll
            for (int kk = 0; kk < 4; kk++) {
                uint32_t a0 = pack_half2(s[2*kk][0],   s[2*kk][1]);
                uint32_t a1 = pack_half2(s[2*kk][2],   s[2*kk][3]);
                uint32_t a2 = pack_half2(s[2*kk+1][0], s[2*kk+1][1]);
                uint32_t a3 = pack_half2(s[2*kk+1][2], s[2*kk+1][3]);
#pragma unroll
                for (int jj = 0; jj < 4; jj++) {
                    uint32_t addr = sVs + (uint32_t)buf * (ABK * VSTR * 2)
                        + (uint32_t)((kk * 16 + (lane & 15)) * VSTR
                                     + jj * 16 + (lane >> 4) * 8) * 2;
                    uint32_t v0, v1, v2, v3;
                    asm volatile(
                        "ldmatrix.sync.aligned.m8n8.x4.trans.shared.b16 {%0,%1,%2,%3}, [%4];"
                        : "=r"(v0), "=r"(v1), "=r"(v2), "=r"(v3) : "r"(addr));
                    asm volatile(
                        "mma.sync.aligned.m16n8k16.row.col.f32.f16.f16.f32 "
                        "{%0,%1,%2,%3}, {%4,%5,%6,%7}, {%8,%9}, {%0,%1,%2,%3};"
                        : "+f"(o[2*jj][0]), "+f"(o[2*jj][1]), "+f"(o[2*jj][2]), "+f"(o[2*jj][3])
                        : "r"(a0), "r"(a1), "r"(a2), "r"(a3), "r"(v0), "r"(v1));
                    asm volatile(
                        "mma.sync.aligned.m16n8k16.row.col.f32.f16.f16.f32 "
                        "{%0,%1,%2,%3}, {%4,%5,%6,%7}, {%8,%9}, {%0,%1,%2,%3};"
                        : "+f"(o[2*jj+1][0]), "+f"(o[2*jj+1][1]), "+f"(o[2*jj+1][2]), "+f"(o[2*jj+1][3])
                        : "r"(a0), "r"(a1), "r"(a2), "r"(a3), "r"(v2), "r"(v3));
                }
            }
        }
        __syncthreads();
        buf ^= 1;
    }

    l0 += __shfl_xor_sync(0xffffffffu, l0, 1);
    l0 += __shfl_xor_sync(0xffffffffu, l0, 2);
    l1 += __shfl_xor_sync(0xffffffffu, l1, 1);
    l1 += __shfl_xor_sync(0xffffffffu, l1, 2);
    const float inv0 = 1.f / l0, inv1 = 1.f / l1;

    __half* o0p = OH + ((size_t)(b * Ss) + wq0 + r) * Dd + h * HD;
    __half* o1p = o0p + 8 * (size_t)Dd;
#pragma unroll
    for (int j = 0; j < 8; j++) {
        int col = j * 8 + 2 * c;
        *(__half2*)&o0p[col] = __floats2half2_rn(o[j][0] * inv0, o[j][1] * inv0);
        *(__half2*)&o1p[col] = __floats2half2_rn(o[j][2] * inv1, o[j][3] * inv1);
    }
}

// ---------------------------------------------------------------------------
// Launch
// ---------------------------------------------------------------------------
extern "C" void kernel_launch(void* const* d_in, const int* in_sizes, int n_in,
                              void* d_out, int out_size)
{
    const float* x       = (const float*)d_in[0];
    const float* Wq      = (const float*)d_in[1];
    const float* Wk      = (const float*)d_in[2];
    const float* Wv      = (const float*)d_in[3];
    const float* Wq_ded  = (const float*)d_in[4];
    const float* Wk_ded  = (const float*)d_in[5];
    const float* Wv_ded  = (const float*)d_in[6];
    const float* Wo      = (const float*)d_in[7];

    float* out_o = (float*)d_out;
    float* out_k = out_o + ELEM;
    float* out_v = out_k + ELEM;

    float  *qbuf = nullptr;
    __half *xh = nullptr, *wth = nullptr, *ah = nullptr;
    __half *qh = nullptr, *kh = nullptr, *vh = nullptr;
    cudaGetSymbolAddress((void**)&qbuf, g_q);
    cudaGetSymbolAddress((void**)&xh,   g_xh);
    cudaGetSymbolAddress((void**)&wth,  g_wth);
    cudaGetSymbolAddress((void**)&ah,   g_ah);
    cudaGetSymbolAddress((void**)&qh,   g_qh);
    cudaGetSymbolAddress((void**)&kh,   g_kh);
    cudaGetSymbolAddress((void**)&vh,   g_vh);
    __half* wtq = wth;
    __half* wtk = wth + (size_t)Dd * Dd;
    __half* wtv = wth + 2 * (size_t)Dd * Dd;
    __half* wto = wth + 3 * (size_t)Dd * Dd;

    cudaFuncSetAttribute(h_gemm_kernel,
                         cudaFuncAttributeMaxDynamicSharedMemorySize, GEMM_SMEM);
    cudaFuncSetAttribute(attn_tc_kernel,
                         cudaFuncAttributeMaxDynamicSharedMemorySize, ATTN_SMEM);

    // 0) x -> fp16; batched transpose+convert of the 4 weight matrices
    cvt_half_kernel<<<2048, 256>>>(x, xh, (int)(ELEM / 4));
    dim3 tg(32, 32, 4), tb(32, 8);
    transpose_h4_kernel<<<tg, tb>>>(Wq, Wk, Wv, Wo, wth);

    // 1) fused Q/K/V shared projections (128x128 tiles, GBK=64, 2 CTAs/SM)
    dim3 gg3(Dd / GBN, TOK / GBM, 3);   // (8, 64, 3)
    h_gemm_kernel<<<gg3, 256, GEMM_SMEM>>>(
        xh, wtq, wtk, wtv, (float*)nullptr, out_k, out_v, qh, kh, vh, Dd);

    // 2) dedicated-weight rows (re-partitioned: 1536 blocks)
    dim3 dg(32, Nn, 3);
    ded_proj_kernel<<<dg, 256>>>(x, Wq_ded, Wk_ded, Wv_ded,
                                 qbuf, out_k, out_v, qh, kh, vh);

    // 3) fully-fp16 tensor-core causal attention (heavy blocks first)
    dim3 ag(Ss / ABQ, Hh, Bb);
    attn_tc_kernel<<<ag, 256, ATTN_SMEM>>>(qh, kh, vh, ah);

    // 4) output projection
    dim3 gg1(Dd / GBN, TOK / GBM, 1);
    h_gemm_kernel<<<gg1, 256, GEMM_SMEM>>>(
        ah, wto, wto, wto, out_o, out_o, out_o,
        (__half*)nullptr, (__half*)nullptr, (__half*)nullptr, Dd);
}

// round 16
// speedup vs baseline: 1.0935x; 1.0935x over previous
#include <cuda_runtime.h>
#include <cuda_bf16.h>
#include <cuda_fp16.h>
#include <math.h>
#include <cstdint>

// Problem constants
#define Bb   8
#define Ss   1024
#define Dd   1024
#define Hh   16
#define HD   64
#define Nn   16
#define TOK  (Bb*Ss)              // 8192
#define ELEM ((size_t)Bb*Ss*Dd)   // 8388608

// Scratch (allocation-free rule: device globals)
__device__ float  g_q[ELEM];                 // fp32 q (ded_proj target; unused downstream)
__device__ __half g_xh[ELEM];                // fp16 x
__device__ __half g_wth[4 * Dd * Dd];        // fp16 transposed Wq,Wk,Wv,Wo
__device__ __half g_ah[ELEM];                // fp16 attention output
__device__ __half g_qh[ELEM];                // fp16 q
__device__ __half g_kh[ELEM];                // fp16 k
__device__ __half g_vh[ELEM];                // fp16 v

__device__ __forceinline__ uint32_t pack_half2(float a, float b) {
    uint32_t r;
    asm("cvt.rn.f16x2.f32 %0, %2, %1;" : "=r"(r) : "f"(a), "f"(b));
    return r;   // low half = a, high half = b
}

// ---------------------------------------------------------------------------
// Elementwise fp32 -> fp16 (x -> xh)
// ---------------------------------------------------------------------------
__global__ __launch_bounds__(256) void cvt_half_kernel(
    const float* __restrict__ in, __half* __restrict__ out, int n4)
{
    int i = blockIdx.x * blockDim.x + threadIdx.x;
    int stride = gridDim.x * blockDim.x;
    for (; i < n4; i += stride) {
        float4 v = ((const float4*)in)[i];
        ((__half2*)out)[2 * i]     = __floats2half2_rn(v.x, v.y);
        ((__half2*)out)[2 * i + 1] = __floats2half2_rn(v.z, v.w);
    }
}

// ---------------------------------------------------------------------------
// Batched W transpose + fp16 convert: out[z][n][k] = half(in[z][k][n])
// ---------------------------------------------------------------------------
__global__ __launch_bounds__(256) void transpose_h4_kernel(
    const float* __restrict__ in0, const float* __restrict__ in1,
    const float* __restrict__ in2, const float* __restrict__ in3,
    __half* __restrict__ out)
{
    __shared__ float t[32][33];
    const float* in = (blockIdx.z == 0) ? in0 : (blockIdx.z == 1 ? in1 :
                      (blockIdx.z == 2) ? in2 : in3);
    __half* dst = out + (size_t)blockIdx.z * Dd * Dd;

    int x = blockIdx.x * 32 + threadIdx.x;
    int y = blockIdx.y * 32 + threadIdx.y;
#pragma unroll
    for (int j = 0; j < 32; j += 8)
        t[threadIdx.y + j][threadIdx.x] = in[(size_t)(y + j) * Dd + x];
    __syncthreads();
    x = blockIdx.y * 32 + threadIdx.x;
    y = blockIdx.x * 32 + threadIdx.y;
#pragma unroll
    for (int j = 0; j < 32; j += 8)
        dst[(size_t)(y + j) * Dd + x] = __float2half_rn(t[threadIdx.x][threadIdx.y + j]);
}

// ---------------------------------------------------------------------------
// fp16 tensor-core GEMM: C[M,Nc] = A[M,K] @ Wt[Nc,K]^T, fp32 accumulate.
// CTA tile 128x128, GBK=64, 256 threads (8 warps, 4m x 2n, warp 32x64),
// NSTAGE=3, ~110KB smem -> 2 CTAs/SM. (R14 winner, unchanged)
// ---------------------------------------------------------------------------
#define GBM 128
#define GBN 128
#define GBK 64
#define ASTR 72
#define NSTAGE 3
#define GEMM_SMEM (NSTAGE * (GBM + GBN) * ASTR * 2)   // 110592 B

__global__ void __launch_bounds__(256, 2)
h_gemm_kernel(const __half* __restrict__ A,
              const __half* __restrict__ Wt0, const __half* __restrict__ Wt1,
              const __half* __restrict__ Wt2,
              float* __restrict__ C0, float* __restrict__ C1,
              float* __restrict__ C2,
              __half* __restrict__ H0, __half* __restrict__ H1,
              __half* __restrict__ H2, int K)
{
    extern __shared__ __half smemh[];
    __half* As = smemh;
    __half* Bs = smemh + NSTAGE * GBM * ASTR;

    const __half* Wt = (blockIdx.z == 0) ? Wt0 : (blockIdx.z == 1 ? Wt1 : Wt2);
    float* C         = (blockIdx.z == 0) ? C0  : (blockIdx.z == 1 ? C1  : C2);
    __half* Hc       = (blockIdx.z == 0) ? H0  : (blockIdx.z == 1 ? H1  : H2);

    const int tid  = threadIdx.x;
    const int lane = tid & 31;
    const int wid  = tid >> 5;
    const int wm   = (wid & 3) * 32;
    const int wn   = (wid >> 2) * 64;
    const int m0   = blockIdx.y * GBM;
    const int n0   = blockIdx.x * GBN;

    const uint32_t sA = (uint32_t)__cvta_generic_to_shared(As);
    const uint32_t sB = (uint32_t)__cvta_generic_to_shared(Bs);

    float acc[2][8][4];
#pragma unroll
    for (int mf = 0; mf < 2; mf++)
#pragma unroll
        for (int nf = 0; nf < 8; nf++)
#pragma unroll
            for (int r = 0; r < 4; r++) acc[mf][nf][r] = 0.f;

    const __half* Abase = A + (size_t)m0 * K;
    const __half* Bbase = Wt + (size_t)n0 * K;

    auto load_tile = [&](int k0, int st) {
        uint32_t dstA = sA + (uint32_t)st * (GBM * ASTR * 2);
#pragma unroll
        for (int j = 0; j < 4; j++) {
            int g = tid + 256 * j;
            int m = g >> 3, c = g & 7;
            const __half* src = Abase + (size_t)m * K + k0 + c * 8;
            asm volatile("cp.async.ca.shared.global [%0], [%1], 16;\n"
                         :: "r"(dstA + (uint32_t)(m * ASTR + c * 8) * 2), "l"(src));
        }
        uint32_t dstB = sB + (uint32_t)st * (GBN * ASTR * 2);
#pragma unroll
        for (int j = 0; j < 4; j++) {
            int g = tid + 256 * j;
            int n = g >> 3, c = g & 7;
            const __half* src = Bbase + (size_t)n * K + k0 + c * 8;
            asm volatile("cp.async.ca.shared.global [%0], [%1], 16;\n"
                         :: "r"(dstB + (uint32_t)(n * ASTR + c * 8) * 2), "l"(src));
        }
    };

    const int ql = lane >> 3, rl = lane & 7;

    auto compute = [&](int st) {
        const uint32_t baseA = sA + (uint32_t)st * (GBM * ASTR * 2);
        const uint32_t baseB = sB + (uint32_t)st * (GBN * ASTR * 2);
#pragma unroll
        for (int t = 0; t < 4; t++) {
            uint32_t a[2][4];
#pragma unroll
            for (int mf = 0; mf < 2; mf++) {
                int mrow = wm + mf * 16 + rl + (ql & 1) * 8;
                int kc   = t * 16 + (ql >> 1) * 8;
                uint32_t addr = baseA + (uint32_t)(mrow * ASTR + kc) * 2;
                asm volatile(
                    "ldmatrix.sync.aligned.m8n8.x4.shared.b16 {%0,%1,%2,%3}, [%4];"
                    : "=r"(a[mf][0]), "=r"(a[mf][1]), "=r"(a[mf][2]), "=r"(a[mf][3])
                    : "r"(addr));
            }
            uint32_t b[4][4];
#pragma unroll
            for (int p = 0; p < 4; p++) {
                int nrow = wn + (2 * p + (ql >> 1)) * 8 + rl;
                int kc   = t * 16 + (ql & 1) * 8;
                uint32_t addr = baseB + (uint32_t)(nrow * ASTR + kc) * 2;
                asm volatile(
                    "ldmatrix.sync.aligned.m8n8.x4.shared.b16 {%0,%1,%2,%3}, [%4];"
                    : "=r"(b[p][0]), "=r"(b[p][1]), "=r"(b[p][2]), "=r"(b[p][3])
                    : "r"(addr));
            }
#pragma unroll
            for (int mf = 0; mf < 2; mf++)
#pragma unroll
                for (int nf = 0; nf < 8; nf++) {
                    uint32_t b0 = b[nf >> 1][(nf & 1) * 2];
                    uint32_t b1 = b[nf >> 1][(nf & 1) * 2 + 1];
                    asm volatile(
                        "mma.sync.aligned.m16n8k16.row.col.f32.f16.f16.f32 "
                        "{%0,%1,%2,%3}, {%4,%5,%6,%7}, {%8,%9}, {%0,%1,%2,%3};"
                        : "+f"(acc[mf][nf][0]), "+f"(acc[mf][nf][1]),
                          "+f"(acc[mf][nf][2]), "+f"(acc[mf][nf][3])
                        : "r"(a[mf][0]), "r"(a[mf][1]), "r"(a[mf][2]), "r"(a[mf][3]),
                          "r"(b0), "r"(b1));
                }
        }
    };

    load_tile(0, 0);
    asm volatile("cp.async.commit_group;");
    load_tile(GBK, 1);
    asm volatile("cp.async.commit_group;");

    const int niter = K / GBK;
    for (int i = 0; i < niter; i++) {
        asm volatile("cp.async.wait_group 1;");
        __syncthreads();
        if ((i + 2) * GBK < K)
            load_tile((i + 2) * GBK, (i + 2) % NSTAGE);
        asm volatile("cp.async.commit_group;");
        compute(i % NSTAGE);
    }

#pragma unroll
    for (int mf = 0; mf < 2; mf++) {
        int row = m0 + wm + mf * 16 + (lane >> 2);
#pragma unroll
        for (int nf = 0; nf < 8; nf++) {
            int col = n0 + wn + nf * 8 + (lane & 3) * 2;
            if (C) {
                *(float2*)&C[(size_t)row * Dd + col] =
                    make_float2(acc[mf][nf][0], acc[mf][nf][1]);
                *(float2*)&C[(size_t)(row + 8) * Dd + col] =
                    make_float2(acc[mf][nf][2], acc[mf][nf][3]);
            }
            if (Hc) {
                *(uint32_t*)&Hc[(size_t)row * Dd + col] =
                    pack_half2(acc[mf][nf][0], acc[mf][nf][1]);
                *(uint32_t*)&Hc[(size_t)(row + 8) * Dd + col] =
                    pack_half2(acc[mf][nf][2], acc[mf][nf][3]);
            }
        }
    }
}

// ---------------------------------------------------------------------------
// Dedicated projection (fused q/k/v) — R14 partition (o-tile 64, 16 k-chunks,
// unroll 8), plus streaming weight loads (__ldcs) and occupancy-pinned regs.
// ---------------------------------------------------------------------------
__global__ __launch_bounds__(256, 3) void ded_proj_kernel(
    const float* __restrict__ x,
    const float* __restrict__ Wq_ded, const float* __restrict__ Wk_ded,
    const float* __restrict__ Wv_ded,
    float* __restrict__ qb, float* __restrict__ kb, float* __restrict__ vb,
    __half* __restrict__ qh, __half* __restrict__ kh, __half* __restrict__ vh)
{
    __shared__ float sm[8192];
    const int n   = blockIdx.y;
    const int o0  = blockIdx.x * 64;
    const int tid = threadIdx.x;
    const float* Wd = (blockIdx.z == 0) ? Wq_ded : (blockIdx.z == 1 ? Wk_ded : Wv_ded);
    float* out      = (blockIdx.z == 0) ? qb     : (blockIdx.z == 1 ? kb     : vb);
    __half* outh    = (blockIdx.z == 0) ? qh     : (blockIdx.z == 1 ? kh     : vh);

    for (int i = tid; i < Bb * Dd; i += 256) {
        int b = i >> 10, k = i & 1023;
        sm[i] = x[((size_t)b * Ss + n) * Dd + k];
    }
    __syncthreads();

    const int of4 = tid & 15;
    const int ks  = tid >> 4;
    const float* Wp = Wd + (size_t)n * Dd * Dd + (size_t)(ks * 64) * Dd + o0 + of4 * 4;

    float acc[8][4];
#pragma unroll
    for (int b = 0; b < 8; b++)
#pragma unroll
        for (int j = 0; j < 4; j++) acc[b][j] = 0.f;

#pragma unroll 8
    for (int kk = 0; kk < 64; kk++) {
        float4 w = __ldcs((const float4*)(Wp + (size_t)kk * Dd));
        int k = ks * 64 + kk;
#pragma unroll
        for (int b = 0; b < 8; b++) {
            float xv = sm[b * 1024 + k];
            acc[b][0] += xv * w.x; acc[b][1] += xv * w.y;
            acc[b][2] += xv * w.z; acc[b][3] += xv * w.w;
        }
    }
    __syncthreads();

#pragma unroll
    for (int b = 0; b < 8; b++)
        *(float4*)&sm[ks * 512 + b * 64 + of4 * 4] =
            make_float4(acc[b][0], acc[b][1], acc[b][2], acc[b][3]);
    __syncthreads();

    for (int p = tid; p < 512; p += 256) {
        int b = p >> 6, ol = p & 63;
        float s = 0.f;
#pragma unroll
        for (int k2 = 0; k2 < 16; k2++) s += sm[k2 * 512 + p];
        size_t idx = ((size_t)b * Ss + n) * Dd + o0 + ol;
        out[idx]  = s;
        outh[idx] = __float2half_rn(s);
    }
}

// ---------------------------------------------------------------------------
// Tensor-core causal flash attention — fully fp16 operands, fp32 softmax/acc.
// (natural block order — heavy-first was neutral/negative in R15)
// ---------------------------------------------------------------------------
#define ABQ 128
#define ABK 64
#define KHSTR 72
#define VSTR  72
#define ATTN_SMEM (2*ABK*KHSTR*2 + 2*ABK*VSTR*2)   // 36864 B

__global__ __launch_bounds__(256) void attn_tc_kernel(
    const __half* __restrict__ Qh, const __half* __restrict__ Kh,
    const __half* __restrict__ Vh, __half* __restrict__ OH)
{
    extern __shared__ char asmem[];
    __half* Ks = (__half*)asmem;
    __half* Vs = (__half*)(asmem + 2 * ABK * KHSTR * 2);

    const int b   = blockIdx.z;
    const int h   = blockIdx.y;
    const int q0  = blockIdx.x * ABQ;
    const int tid = threadIdx.x;
    const int lane = tid & 31;
    const int wid  = tid >> 5;
    const int wq0  = q0 + wid * 16;
    const int r = lane >> 2;
    const int c = lane & 3;

    const uint32_t sKs = (uint32_t)__cvta_generic_to_shared(Ks);
    const uint32_t sVs = (uint32_t)__cvta_generic_to_shared(Vs);

    uint32_t qf[4][4];
    {
        const __half* q0p = Qh + ((size_t)(b * Ss) + wq0 + r) * Dd + h * HD;
        const __half* q1p = q0p + 8 * (size_t)Dd;
#pragma unroll
        for (int t = 0; t < 4; t++) {
            qf[t][0] = *(const uint32_t*)&q0p[t * 16 + 2 * c];
            qf[t][1] = *(const uint32_t*)&q1p[t * 16 + 2 * c];
            qf[t][2] = *(const uint32_t*)&q0p[t * 16 + 2 * c + 8];
            qf[t][3] = *(const uint32_t*)&q1p[t * 16 + 2 * c + 8];
        }
    }

    const __half* Kbase = Kh + (size_t)(b * Ss) * Dd + h * HD;
    const __half* Vbase = Vh + (size_t)(b * Ss) * Dd + h * HD;

    auto load_k = [&](int k0, int buf) {
        uint32_t dst = sKs + (uint32_t)buf * (ABK * KHSTR * 2);
#pragma unroll
        for (int j = 0; j < 2; j++) {
            int g = tid + 256 * j;
            int row = g >> 3, c8 = g & 7;
            const __half* src = Kbase + (size_t)(k0 + row) * Dd + c8 * 8;
            asm volatile("cp.async.ca.shared.global [%0], [%1], 16;\n"
                         :: "r"(dst + (uint32_t)(row * KHSTR + c8 * 8) * 2), "l"(src));
        }
    };
    auto load_v = [&](int k0, int buf) {
        uint32_t dst = sVs + (uint32_t)buf * (ABK * VSTR * 2);
#pragma unroll
        for (int j = 0; j < 2; j++) {
            int g = tid + 256 * j;
            int row = g >> 3, c8 = g & 7;
            const __half* src = Vbase + (size_t)(k0 + row) * Dd + c8 * 8;
            asm volatile("cp.async.ca.shared.global [%0], [%1], 16;\n"
                         :: "r"(dst + (uint32_t)(row * VSTR + c8 * 8) * 2), "l"(src));
        }
    };

    float o[8][4];
#pragma unroll
    for (int j = 0; j < 8; j++)
#pragma unroll
        for (int e = 0; e < 4; e++) o[j][e] = 0.f;
    float m0 = -1e30f, m1 = -1e30f, l0 = 0.f, l1 = 0.f;

    const int kend = q0 + ABQ;
    load_k(0, 0);
    load_v(0, 0);
    asm volatile("cp.async.commit_group;");

    int buf = 0;
    const int ql = lane >> 3, rl = lane & 7;

    for (int k0 = 0; k0 < kend; k0 += ABK) {
        asm volatile("cp.async.wait_group 0;");
        __syncthreads();
        if (k0 + ABK < kend) {
            load_k(k0 + ABK, buf ^ 1);
            load_v(k0 + ABK, buf ^ 1);
            asm volatile("cp.async.commit_group;");
        }

        if (k0 <= wq0 + 15) {
            float s[8][4];
#pragma unroll
            for (int j = 0; j < 8; j++)
#pragma unroll
                for (int e = 0; e < 4; e++) s[j][e] = 0.f;

            const uint32_t baseK = sKs + (uint32_t)buf * (ABK * KHSTR * 2);
#pragma unroll
            for (int t = 0; t < 4; t++) {
                uint32_t bk[4][4];
#pragma unroll
                for (int p = 0; p < 4; p++) {
                    int nrow = (2 * p + (ql >> 1)) * 8 + rl;
                    int kc   = t * 16 + (ql & 1) * 8;
                    uint32_t addr = baseK + (uint32_t)(nrow * KHSTR + kc) * 2;
                    asm volatile(
                        "ldmatrix.sync.aligned.m8n8.x4.shared.b16 {%0,%1,%2,%3}, [%4];"
                        : "=r"(bk[p][0]), "=r"(bk[p][1]), "=r"(bk[p][2]), "=r"(bk[p][3])
                        : "r"(addr));
                }
#pragma unroll
                for (int j = 0; j < 8; j++) {
                    uint32_t b0 = bk[j >> 1][(j & 1) * 2];
                    uint32_t b1 = bk[j >> 1][(j & 1) * 2 + 1];
                    asm volatile(
                        "mma.sync.aligned.m16n8k16.row.col.f32.f16.f16.f32 "
                        "{%0,%1,%2,%3}, {%4,%5,%6,%7}, {%8,%9}, {%0,%1,%2,%3};"
                        : "+f"(s[j][0]), "+f"(s[j][1]), "+f"(s[j][2]), "+f"(s[j][3])
                        : "r"(qf[t][0]), "r"(qf[t][1]), "r"(qf[t][2]), "r"(qf[t][3]),
                          "r"(b0), "r"(b1));
                }
            }

            const bool need_mask = (k0 + 63 > wq0);
            float rmax0 = -1e30f, rmax1 = -1e30f;
#pragma unroll
            for (int j = 0; j < 8; j++) {
#pragma unroll
                for (int e = 0; e < 2; e++) {
                    float v0 = s[j][e]     * 0.125f;
                    float v1 = s[j][2 + e] * 0.125f;
                    if (need_mask) {
                        int col = k0 + j * 8 + 2 * c + e;
                        if (col > wq0 + r)     v0 = -1e30f;
                        if (col > wq0 + r + 8) v1 = -1e30f;
                    }
                    s[j][e] = v0; s[j][2 + e] = v1;
                    rmax0 = fmaxf(rmax0, v0);
                    rmax1 = fmaxf(rmax1, v1);
                }
            }
            rmax0 = fmaxf(rmax0, __shfl_xor_sync(0xffffffffu, rmax0, 1));
            rmax0 = fmaxf(rmax0, __shfl_xor_sync(0xffffffffu, rmax0, 2));
            rmax1 = fmaxf(rmax1, __shfl_xor_sync(0xffffffffu, rmax1, 1));
            rmax1 = fmaxf(rmax1, __shfl_xor_sync(0xffffffffu, rmax1, 2));

            float mn0 = fmaxf(m0, rmax0), mn1 = fmaxf(m1, rmax1);
            float corr0 = __expf(m0 - mn0), corr1 = __expf(m1 - mn1);
            m0 = mn0; m1 = mn1;

            float ls0 = 0.f, ls1 = 0.f;
#pragma unroll
            for (int j = 0; j < 8; j++) {
                s[j][0] = __expf(s[j][0] - mn0);
                s[j][1] = __expf(s[j][1] - mn0);
                s[j][2] = __expf(s[j][2] - mn1);
                s[j][3] = __expf(s[j][3] - mn1);
                ls0 += s[j][0] + s[j][1];
                ls1 += s[j][2] + s[j][3];
            }
            l0 = l0 * corr0 + ls0;
            l1 = l1 * corr1 + ls1;
#pragma unroll
            for (int j = 0; j < 8; j++) {
                o[j][0] *= corr0; o[j][1] *= corr0;
                o[j][2] *= corr1; o[j][3] *= corr1;
            }

#pragma unroll
            for (int kk = 0; kk < 4; kk++) {
                uint32_t a0 = pack_half2(s[2*kk][0],   s[2*kk][1]);
                uint32_t a1 = pack_half2(s[2*kk][2],   s[2*kk][3]);
                uint32_t a2 = pack_half2(s[2*kk+1][0], s[2*kk+1][1]);
                uint32_t a3 = pack_half2(s[2*kk+1][2], s[2*kk+1][3]);
#pragma unroll
                for (int jj = 0; jj < 4; jj++) {
                    uint32_t addr = sVs + (uint32_t)buf * (ABK * VSTR * 2)
                        + (uint32_t)((kk * 16 + (lane & 15)) * VSTR
                                     + jj * 16 + (lane >> 4) * 8) * 2;
                    uint32_t v0, v1, v2, v3;
                    asm volatile(
                        "ldmatrix.sync.aligned.m8n8.x4.trans.shared.b16 {%0,%1,%2,%3}, [%4];"
                        : "=r"(v0), "=r"(v1), "=r"(v2), "=r"(v3) : "r"(addr));
                    asm volatile(
                        "mma.sync.aligned.m16n8k16.row.col.f32.f16.f16.f32 "
                        "{%0,%1,%2,%3}, {%4,%5,%6,%7}, {%8,%9}, {%0,%1,%2,%3};"
                        : "+f"(o[2*jj][0]), "+f"(o[2*jj][1]), "+f"(o[2*jj][2]), "+f"(o[2*jj][3])
                        : "r"(a0), "r"(a1), "r"(a2), "r"(a3), "r"(v0), "r"(v1));
                    asm volatile(
                        "mma.sync.aligned.m16n8k16.row.col.f32.f16.f16.f32 "
                        "{%0,%1,%2,%3}, {%4,%5,%6,%7}, {%8,%9}, {%0,%1,%2,%3};"
                        : "+f"(o[2*jj+1][0]), "+f"(o[2*jj+1][1]), "+f"(o[2*jj+1][2]), "+f"(o[2*jj+1][3])
                        : "r"(a0), "r"(a1), "r"(a2), "r"(a3), "r"(v2), "r"(v3));
                }
            }
        }
        __syncthreads();
        buf ^= 1;
    }

    l0 += __shfl_xor_sync(0xffffffffu, l0, 1);
    l0 += __shfl_xor_sync(0xffffffffu, l0, 2);
    l1 += __shfl_xor_sync(0xffffffffu, l1, 1);
    l1 += __shfl_xor_sync(0xffffffffu, l1, 2);
    const float inv0 = 1.f / l0, inv1 = 1.f / l1;

    __half* o0p = OH + ((size_t)(b * Ss) + wq0 + r) * Dd + h * HD;
    __half* o1p = o0p + 8 * (size_t)Dd;
#pragma unroll
    for (int j = 0; j < 8; j++) {
        int col = j * 8 + 2 * c;
        *(__half2*)&o0p[col] = __floats2half2_rn(o[j][0] * inv0, o[j][1] * inv0);
        *(__half2*)&o1p[col] = __floats2half2_rn(o[j][2] * inv1, o[j][3] * inv1);
    }
}

// ---------------------------------------------------------------------------
// Launch
// ---------------------------------------------------------------------------
extern "C" void kernel_launch(void* const* d_in, const int* in_sizes, int n_in,
                              void* d_out, int out_size)
{
    const float* x       = (const float*)d_in[0];
    const float* Wq      = (const float*)d_in[1];
    const float* Wk      = (const float*)d_in[2];
    const float* Wv      = (const float*)d_in[3];
    const float* Wq_ded  = (const float*)d_in[4];
    const float* Wk_ded  = (const float*)d_in[5];
    const float* Wv_ded  = (const float*)d_in[6];
    const float* Wo      = (const float*)d_in[7];

    float* out_o = (float*)d_out;
    float* out_k = out_o + ELEM;
    float* out_v = out_k + ELEM;

    float  *qbuf = nullptr;
    __half *xh = nullptr, *wth = nullptr, *ah = nullptr;
    __half *qh = nullptr, *kh = nullptr, *vh = nullptr;
    cudaGetSymbolAddress((void**)&qbuf, g_q);
    cudaGetSymbolAddress((void**)&xh,   g_xh);
    cudaGetSymbolAddress((void**)&wth,  g_wth);
    cudaGetSymbolAddress((void**)&ah,   g_ah);
    cudaGetSymbolAddress((void**)&qh,   g_qh);
    cudaGetSymbolAddress((void**)&kh,   g_kh);
    cudaGetSymbolAddress((void**)&vh,   g_vh);
    __half* wtq = wth;
    __half* wtk = wth + (size_t)Dd * Dd;
    __half* wtv = wth + 2 * (size_t)Dd * Dd;
    __half* wto = wth + 3 * (size_t)Dd * Dd;

    cudaFuncSetAttribute(h_gemm_kernel,
                         cudaFuncAttributeMaxDynamicSharedMemorySize, GEMM_SMEM);
    cudaFuncSetAttribute(attn_tc_kernel,
                         cudaFuncAttributeMaxDynamicSharedMemorySize, ATTN_SMEM);

    // 0) x -> fp16; batched transpose+convert of the 4 weight matrices
    cvt_half_kernel<<<2048, 256>>>(x, xh, (int)(ELEM / 4));
    dim3 tg(32, 32, 4), tb(32, 8);
    transpose_h4_kernel<<<tg, tb>>>(Wq, Wk, Wv, Wo, wth);

    // 1) fused Q/K/V shared projections (128x128 tiles, GBK=64, 2 CTAs/SM)
    dim3 gg3(Dd / GBN, TOK / GBM, 3);   // (8, 64, 3)
    h_gemm_kernel<<<gg3, 256, GEMM_SMEM>>>(
        xh, wtq, wtk, wtv, (float*)nullptr, out_k, out_v, qh, kh, vh, Dd);

    // 2) dedicated-weight rows (R14 partition + streaming loads)
    dim3 dg(16, Nn, 3);
    ded_proj_kernel<<<dg, 256>>>(x, Wq_ded, Wk_ded, Wv_ded,
                                 qbuf, out_k, out_v, qh, kh, vh);

    // 3) fully-fp16 tensor-core causal attention
    dim3 ag(Ss / ABQ, Hh, Bb);
    attn_tc_kernel<<<ag, 256, ATTN_SMEM>>>(qh, kh, vh, ah);

    // 4) output projection
    dim3 gg1(Dd / GBN, TOK / GBM, 1);
    h_gemm_kernel<<<gg1, 256, GEMM_SMEM>>>(
        ah, wto, wto, wto, out_o, out_o, out_o,
        (__half*)nullptr, (__half*)nullptr, (__half*)nullptr, Dd);
}

// round 17
// speedup vs baseline: 1.1107x; 1.0157x over previous
#include <cuda_runtime.h>
#include <cuda_bf16.h>
#include <cuda_fp16.h>
#include <math.h>
#include <cstdint>

// Problem constants
#define Bb   8
#define Ss   1024
#define Dd   1024
#define Hh   16
#define HD   64
#define Nn   16
#define TOK  (Bb*Ss)              // 8192
#define ELEM ((size_t)Bb*Ss*Dd)   // 8388608

// Scratch (allocation-free rule: device globals)
__device__ __half g_xh[ELEM];                // fp16 x
__device__ __half g_wth[4 * Dd * Dd];        // fp16 transposed Wq,Wk,Wv,Wo
__device__ __half g_ah[ELEM];                // fp16 attention output
__device__ __half g_qh[ELEM];                // fp16 q
__device__ __half g_kh[ELEM];                // fp16 k
__device__ __half g_vh[ELEM];                // fp16 v

__device__ __forceinline__ uint32_t pack_half2(float a, float b) {
    uint32_t r;
    asm("cvt.rn.f16x2.f32 %0, %2, %1;" : "=r"(r) : "f"(a), "f"(b));
    return r;   // low half = a, high half = b
}

// ---------------------------------------------------------------------------
// Elementwise fp32 -> fp16 (x -> xh)
// ---------------------------------------------------------------------------
__global__ __launch_bounds__(256) void cvt_half_kernel(
    const float* __restrict__ in, __half* __restrict__ out, int n4)
{
    int i = blockIdx.x * blockDim.x + threadIdx.x;
    int stride = gridDim.x * blockDim.x;
    for (; i < n4; i += stride) {
        float4 v = ((const float4*)in)[i];
        ((__half2*)out)[2 * i]     = __floats2half2_rn(v.x, v.y);
        ((__half2*)out)[2 * i + 1] = __floats2half2_rn(v.z, v.w);
    }
}

// ---------------------------------------------------------------------------
// Batched W transpose + fp16 convert: out[z][n][k] = half(in[z][k][n])
// ---------------------------------------------------------------------------
__global__ __launch_bounds__(256) void transpose_h4_kernel(
    const float* __restrict__ in0, const float* __restrict__ in1,
    const float* __restrict__ in2, const float* __restrict__ in3,
    __half* __restrict__ out)
{
    __shared__ float t[32][33];
    const float* in = (blockIdx.z == 0) ? in0 : (blockIdx.z == 1 ? in1 :
                      (blockIdx.z == 2) ? in2 : in3);
    __half* dst = out + (size_t)blockIdx.z * Dd * Dd;

    int x = blockIdx.x * 32 + threadIdx.x;
    int y = blockIdx.y * 32 + threadIdx.y;
#pragma unroll
    for (int j = 0; j < 32; j += 8)
        t[threadIdx.y + j][threadIdx.x] = in[(size_t)(y + j) * Dd + x];
    __syncthreads();
    x = blockIdx.y * 32 + threadIdx.x;
    y = blockIdx.x * 32 + threadIdx.y;
#pragma unroll
    for (int j = 0; j < 32; j += 8)
        dst[(size_t)(y + j) * Dd + x] = __float2half_rn(t[threadIdx.x][threadIdx.y + j]);
}

// ---------------------------------------------------------------------------
// GEMM config (shared by fused QKV+ded kernel and the O-projection kernel)
// CTA tile 128x128, GBK=64, 8 warps (4m x 2n, warp 32x64), NSTAGE=3.
// ---------------------------------------------------------------------------
#define GBM 128
#define GBN 128
#define GBK 64
#define ASTR 72
#define NSTAGE 3
#define GEMM_SMEM (NSTAGE * (GBM + GBN) * ASTR * 2)   // 110592 B

// Common GEMM device body. skip_ded: skip output rows with (row&1023) < Nn.
template<bool SKIP_DED>
__device__ __forceinline__ void gemm_body(
    const __half* __restrict__ A, const __half* __restrict__ Wt,
    float* __restrict__ C, __half* __restrict__ Hc,
    int m0, int n0, __half* smemh)
{
    __half* As = smemh;
    __half* Bs = smemh + NSTAGE * GBM * ASTR;

    const int tid  = threadIdx.x;
    const int lane = tid & 31;
    const int wid  = tid >> 5;
    const int wm   = (wid & 3) * 32;
    const int wn   = (wid >> 2) * 64;

    const uint32_t sA = (uint32_t)__cvta_generic_to_shared(As);
    const uint32_t sB = (uint32_t)__cvta_generic_to_shared(Bs);

    float acc[2][8][4];
#pragma unroll
    for (int mf = 0; mf < 2; mf++)
#pragma unroll
        for (int nf = 0; nf < 8; nf++)
#pragma unroll
            for (int r = 0; r < 4; r++) acc[mf][nf][r] = 0.f;

    const __half* Abase = A + (size_t)m0 * Dd;
    const __half* Bbase = Wt + (size_t)n0 * Dd;

    auto load_tile = [&](int k0, int st) {
        uint32_t dstA = sA + (uint32_t)st * (GBM * ASTR * 2);
#pragma unroll
        for (int j = 0; j < 4; j++) {
            int g = tid + 256 * j;
            int m = g >> 3, c = g & 7;
            const __half* src = Abase + (size_t)m * Dd + k0 + c * 8;
            asm volatile("cp.async.ca.shared.global [%0], [%1], 16;\n"
                         :: "r"(dstA + (uint32_t)(m * ASTR + c * 8) * 2), "l"(src));
        }
        uint32_t dstB = sB + (uint32_t)st * (GBN * ASTR * 2);
#pragma unroll
        for (int j = 0; j < 4; j++) {
            int g = tid + 256 * j;
            int n = g >> 3, c = g & 7;
            const __half* src = Bbase + (size_t)n * Dd + k0 + c * 8;
            asm volatile("cp.async.ca.shared.global [%0], [%1], 16;\n"
                         :: "r"(dstB + (uint32_t)(n * ASTR + c * 8) * 2), "l"(src));
        }
    };

    const int ql = lane >> 3, rl = lane & 7;

    auto compute = [&](int st) {
        const uint32_t baseA = sA + (uint32_t)st * (GBM * ASTR * 2);
        const uint32_t baseB = sB + (uint32_t)st * (GBN * ASTR * 2);
#pragma unroll
        for (int t = 0; t < 4; t++) {
            uint32_t a[2][4];
#pragma unroll
            for (int mf = 0; mf < 2; mf++) {
                int mrow = wm + mf * 16 + rl + (ql & 1) * 8;
                int kc   = t * 16 + (ql >> 1) * 8;
                uint32_t addr = baseA + (uint32_t)(mrow * ASTR + kc) * 2;
                asm volatile(
                    "ldmatrix.sync.aligned.m8n8.x4.shared.b16 {%0,%1,%2,%3}, [%4];"
                    : "=r"(a[mf][0]), "=r"(a[mf][1]), "=r"(a[mf][2]), "=r"(a[mf][3])
                    : "r"(addr));
            }
            uint32_t b[4][4];
#pragma unroll
            for (int p = 0; p < 4; p++) {
                int nrow = wn + (2 * p + (ql >> 1)) * 8 + rl;
                int kc   = t * 16 + (ql & 1) * 8;
                uint32_t addr = baseB + (uint32_t)(nrow * ASTR + kc) * 2;
                asm volatile(
                    "ldmatrix.sync.aligned.m8n8.x4.shared.b16 {%0,%1,%2,%3}, [%4];"
                    : "=r"(b[p][0]), "=r"(b[p][1]), "=r"(b[p][2]), "=r"(b[p][3])
                    : "r"(addr));
            }
#pragma unroll
            for (int mf = 0; mf < 2; mf++)
#pragma unroll
                for (int nf = 0; nf < 8; nf++) {
                    uint32_t b0 = b[nf >> 1][(nf & 1) * 2];
                    uint32_t b1 = b[nf >> 1][(nf & 1) * 2 + 1];
                    asm volatile(
                        "mma.sync.aligned.m16n8k16.row.col.f32.f16.f16.f32 "
                        "{%0,%1,%2,%3}, {%4,%5,%6,%7}, {%8,%9}, {%0,%1,%2,%3};"
                        : "+f"(acc[mf][nf][0]), "+f"(acc[mf][nf][1]),
                          "+f"(acc[mf][nf][2]), "+f"(acc[mf][nf][3])
                        : "r"(a[mf][0]), "r"(a[mf][1]), "r"(a[mf][2]), "r"(a[mf][3]),
                          "r"(b0), "r"(b1));
                }
        }
    };

    load_tile(0, 0);
    asm volatile("cp.async.commit_group;");
    load_tile(GBK, 1);
    asm volatile("cp.async.commit_group;");

    const int niter = Dd / GBK;
    for (int i = 0; i < niter; i++) {
        asm volatile("cp.async.wait_group 1;");
        __syncthreads();
        if ((i + 2) * GBK < Dd)
            load_tile((i + 2) * GBK, (i + 2) % NSTAGE);
        asm volatile("cp.async.commit_group;");
        compute(i % NSTAGE);
    }

#pragma unroll
    for (int mf = 0; mf < 2; mf++) {
        int row = m0 + wm + mf * 16 + (lane >> 2);
#pragma unroll
        for (int nf = 0; nf < 8; nf++) {
            int col = n0 + wn + nf * 8 + (lane & 3) * 2;
            bool ok0 = !SKIP_DED || ((row & 1023) >= Nn);
            bool ok1 = !SKIP_DED || (((row + 8) & 1023) >= Nn);
            if (C) {
                if (ok0)
                    *(float2*)&C[(size_t)row * Dd + col] =
                        make_float2(acc[mf][nf][0], acc[mf][nf][1]);
                if (ok1)
                    *(float2*)&C[(size_t)(row + 8) * Dd + col] =
                        make_float2(acc[mf][nf][2], acc[mf][nf][3]);
            }
            if (Hc) {
                if (ok0)
                    *(uint32_t*)&Hc[(size_t)row * Dd + col] =
                        pack_half2(acc[mf][nf][0], acc[mf][nf][1]);
                if (ok1)
                    *(uint32_t*)&Hc[(size_t)(row + 8) * Dd + col] =
                        pack_half2(acc[mf][nf][2], acc[mf][nf][3]);
            }
        }
    }
}

// ded_proj device body (R16 winner: o-tile 64, 16 k-chunks, unroll 8, __ldcs)
__device__ __forceinline__ void ded_body(
    const float* __restrict__ x, const float* __restrict__ Wd,
    float* __restrict__ out, __half* __restrict__ outh,
    int n, int o0, float* sm)
{
    const int tid = threadIdx.x;

    for (int i = tid; i < Bb * Dd; i += 256) {
        int b = i >> 10, k = i & 1023;
        sm[i] = x[((size_t)b * Ss + n) * Dd + k];
    }
    __syncthreads();

    const int of4 = tid & 15;
    const int ks  = tid >> 4;
    const float* Wp = Wd + (size_t)n * Dd * Dd + (size_t)(ks * 64) * Dd + o0 + of4 * 4;

    float acc[8][4];
#pragma unroll
    for (int b = 0; b < 8; b++)
#pragma unroll
        for (int j = 0; j < 4; j++) acc[b][j] = 0.f;

#pragma unroll 8
    for (int kk = 0; kk < 64; kk++) {
        float4 w = __ldcs((const float4*)(Wp + (size_t)kk * Dd));
        int k = ks * 64 + kk;
#pragma unroll
        for (int b = 0; b < 8; b++) {
            float xv = sm[b * 1024 + k];
            acc[b][0] += xv * w.x; acc[b][1] += xv * w.y;
            acc[b][2] += xv * w.z; acc[b][3] += xv * w.w;
        }
    }
    __syncthreads();

#pragma unroll
    for (int b = 0; b < 8; b++)
        *(float4*)&sm[ks * 512 + b * 64 + of4 * 4] =
            make_float4(acc[b][0], acc[b][1], acc[b][2], acc[b][3]);
    __syncthreads();

    for (int p = tid; p < 512; p += 256) {
        int b = p >> 6, ol = p & 63;
        float s = 0.f;
#pragma unroll
        for (int k2 = 0; k2 < 16; k2++) s += sm[k2 * 512 + p];
        size_t idx = ((size_t)b * Ss + n) * Dd + o0 + ol;
        if (out) out[idx] = s;
        outh[idx] = __float2half_rn(s);
    }
}

// ---------------------------------------------------------------------------
// Fused QKV GEMM + dedicated projection. 1D grid of 2304 blocks,
// striped: idx%3==1 -> ded (768 blocks), else GEMM (1536 blocks).
// GEMM skips token-rows < 16 (ded owns them) => no ordering dependency.
// ---------------------------------------------------------------------------
__global__ void __launch_bounds__(256, 2)
fused_qkv_ded_kernel(const __half* __restrict__ A,
                     const __half* __restrict__ Wt0, const __half* __restrict__ Wt1,
                     const __half* __restrict__ Wt2,
                     const float* __restrict__ x,
                     const float* __restrict__ Wq_ded,
                     const float* __restrict__ Wk_ded,
                     const float* __restrict__ Wv_ded,
                     float* __restrict__ Ck, float* __restrict__ Cv,
                     __half* __restrict__ Hq, __half* __restrict__ Hk,
                     __half* __restrict__ Hv)
{
    extern __shared__ __half smemh[];
    const int idx = blockIdx.x;
    const int mod = idx % 3;

    if (mod == 1) {
        // ded block: d in [0, 768)
        const int d  = idx / 3;
        const int o0 = (d & 15) * 64;
        const int n  = (d >> 4) & 15;
        const int z  = d >> 8;
        const float* Wd = (z == 0) ? Wq_ded : (z == 1 ? Wk_ded : Wv_ded);
        float* out      = (z == 0) ? (float*)nullptr : (z == 1 ? Ck : Cv);
        __half* outh    = (z == 0) ? Hq : (z == 1 ? Hk : Hv);
        ded_body(x, Wd, out, outh, n, o0, (float*)smemh);
    } else {
        // GEMM block: g in [0, 1536)
        const int g  = (idx / 3) * 2 + (mod >> 1);
        const int n0 = (g & 7) * GBN;
        const int m0 = ((g >> 3) & 63) * GBM;
        const int z  = g >> 9;
        const __half* Wt = (z == 0) ? Wt0 : (z == 1 ? Wt1 : Wt2);
        float* C         = (z == 0) ? (float*)nullptr : (z == 1 ? Ck : Cv);
        __half* Hc       = (z == 0) ? Hq : (z == 1 ? Hk : Hv);
        gemm_body<true>(A, Wt, C, Hc, m0, n0, smemh);
    }
}

// ---------------------------------------------------------------------------
// Plain GEMM kernel for the O projection (no row skipping).
// ---------------------------------------------------------------------------
__global__ void __launch_bounds__(256, 2)
h_gemm_kernel(const __half* __restrict__ A, const __half* __restrict__ Wt,
              float* __restrict__ C)
{
    extern __shared__ __half smemh[];
    gemm_body<false>(A, Wt, C, (__half*)nullptr,
                     blockIdx.y * GBM, blockIdx.x * GBN, smemh);
}

// ---------------------------------------------------------------------------
// Tensor-core causal flash attention — fully fp16 operands, fp32 softmax/acc.
// ---------------------------------------------------------------------------
#define ABQ 128
#define ABK 64
#define KHSTR 72
#define VSTR  72
#define ATTN_SMEM (2*ABK*KHSTR*2 + 2*ABK*VSTR*2)   // 36864 B

__global__ __launch_bounds__(256) void attn_tc_kernel(
    const __half* __restrict__ Qh, const __half* __restrict__ Kh,
    const __half* __restrict__ Vh, __half* __restrict__ OH)
{
    extern __shared__ char asmem[];
    __half* Ks = (__half*)asmem;
    __half* Vs = (__half*)(asmem + 2 * ABK * KHSTR * 2);

    const int b   = blockIdx.z;
    const int h   = blockIdx.y;
    const int q0  = blockIdx.x * ABQ;
    const int tid = threadIdx.x;
    const int lane = tid & 31;
    const int wid  = tid >> 5;
    const int wq0  = q0 + wid * 16;
    const int r = lane >> 2;
    const int c = lane & 3;

    const uint32_t sKs = (uint32_t)__cvta_generic_to_shared(Ks);
    const uint32_t sVs = (uint32_t)__cvta_generic_to_shared(Vs);

    uint32_t qf[4][4];
    {
        const __half* q0p = Qh + ((size_t)(b * Ss) + wq0 + r) * Dd + h * HD;
        const __half* q1p = q0p + 8 * (size_t)Dd;
#pragma unroll
        for (int t = 0; t < 4; t++) {
            qf[t][0] = *(const uint32_t*)&q0p[t * 16 + 2 * c];
            qf[t][1] = *(const uint32_t*)&q1p[t * 16 + 2 * c];
            qf[t][2] = *(const uint32_t*)&q0p[t * 16 + 2 * c + 8];
            qf[t][3] = *(const uint32_t*)&q1p[t * 16 + 2 * c + 8];
        }
    }

    const __half* Kbase = Kh + (size_t)(b * Ss) * Dd + h * HD;
    const __half* Vbase = Vh + (size_t)(b * Ss) * Dd + h * HD;

    auto load_k = [&](int k0, int buf) {
        uint32_t dst = sKs + (uint32_t)buf * (ABK * KHSTR * 2);
#pragma unroll
        for (int j = 0; j < 2; j++) {
            int g = tid + 256 * j;
            int row = g >> 3, c8 = g & 7;
            const __half* src = Kbase + (size_t)(k0 + row) * Dd + c8 * 8;
            asm volatile("cp.async.ca.shared.global [%0], [%1], 16;\n"
                         :: "r"(dst + (uint32_t)(row * KHSTR + c8 * 8) * 2), "l"(src));
        }
    };
    auto load_v = [&](int k0, int buf) {
        uint32_t dst = sVs + (uint32_t)buf * (ABK * VSTR * 2);
#pragma unroll
        for (int j = 0; j < 2; j++) {
            int g = tid + 256 * j;
            int row = g >> 3, c8 = g & 7;
            const __half* src = Vbase + (size_t)(k0 + row) * Dd + c8 * 8;
            asm volatile("cp.async.ca.shared.global [%0], [%1], 16;\n"
                         :: "r"(dst + (uint32_t)(row * VSTR + c8 * 8) * 2), "l"(src));
        }
    };

    float o[8][4];
#pragma unroll
    for (int j = 0; j < 8; j++)
#pragma unroll
        for (int e = 0; e < 4; e++) o[j][e] = 0.f;
    float m0 = -1e30f, m1 = -1e30f, l0 = 0.f, l1 = 0.f;

    const int kend = q0 + ABQ;
    load_k(0, 0);
    load_v(0, 0);
    asm volatile("cp.async.commit_group;");

    int buf = 0;
    const int ql = lane >> 3, rl = lane & 7;

    for (int k0 = 0; k0 < kend; k0 += ABK) {
        asm volatile("cp.async.wait_group 0;");
        __syncthreads();
        if (k0 + ABK < kend) {
            load_k(k0 + ABK, buf ^ 1);
            load_v(k0 + ABK, buf ^ 1);
            asm volatile("cp.async.commit_group;");
        }

        if (k0 <= wq0 + 15) {
            float s[8][4];
#pragma unroll
            for (int j = 0; j < 8; j++)
#pragma unroll
                for (int e = 0; e < 4; e++) s[j][e] = 0.f;

            const uint32_t baseK = sKs + (uint32_t)buf * (ABK * KHSTR * 2);
#pragma unroll
            for (int t = 0; t < 4; t++) {
                uint32_t bk[4][4];
#pragma unroll
                for (int p = 0; p < 4; p++) {
                    int nrow = (2 * p + (ql >> 1)) * 8 + rl;
                    int kc   = t * 16 + (ql & 1) * 8;
                    uint32_t addr = baseK + (uint32_t)(nrow * KHSTR + kc) * 2;
                    asm volatile(
                        "ldmatrix.sync.aligned.m8n8.x4.shared.b16 {%0,%1,%2,%3}, [%4];"
                        : "=r"(bk[p][0]), "=r"(bk[p][1]), "=r"(bk[p][2]), "=r"(bk[p][3])
                        : "r"(addr));
                }
#pragma unroll
                for (int j = 0; j < 8; j++) {
                    uint32_t b0 = bk[j >> 1][(j & 1) * 2];
                    uint32_t b1 = bk[j >> 1][(j & 1) * 2 + 1];
                    asm volatile(
                        "mma.sync.aligned.m16n8k16.row.col.f32.f16.f16.f32 "
                        "{%0,%1,%2,%3}, {%4,%5,%6,%7}, {%8,%9}, {%0,%1,%2,%3};"
                        : "+f"(s[j][0]), "+f"(s[j][1]), "+f"(s[j][2]), "+f"(s[j][3])
                        : "r"(qf[t][0]), "r"(qf[t][1]), "r"(qf[t][2]), "r"(qf[t][3]),
                          "r"(b0), "r"(b1));
                }
            }

            const bool need_mask = (k0 + 63 > wq0);
            float rmax0 = -1e30f, rmax1 = -1e30f;
#pragma unroll
            for (int j = 0; j < 8; j++) {
#pragma unroll
                for (int e = 0; e < 2; e++) {
                    float v0 = s[j][e]     * 0.125f;
                    float v1 = s[j][2 + e] * 0.125f;
                    if (need_mask) {
                        int col = k0 + j * 8 + 2 * c + e;
                        if (col > wq0 + r)     v0 = -1e30f;
                        if (col > wq0 + r + 8) v1 = -1e30f;
                    }
                    s[j][e] = v0; s[j][2 + e] = v1;
                    rmax0 = fmaxf(rmax0, v0);
                    rmax1 = fmaxf(rmax1, v1);
                }
            }
            rmax0 = fmaxf(rmax0, __shfl_xor_sync(0xffffffffu, rmax0, 1));
            rmax0 = fmaxf(rmax0, __shfl_xor_sync(0xffffffffu, rmax0, 2));
            rmax1 = fmaxf(rmax1, __shfl_xor_sync(0xffffffffu, rmax1, 1));
            rmax1 = fmaxf(rmax1, __shfl_xor_sync(0xffffffffu, rmax1, 2));

            float mn0 = fmaxf(m0, rmax0), mn1 = fmaxf(m1, rmax1);
            float corr0 = __expf(m0 - mn0), corr1 = __expf(m1 - mn1);
            m0 = mn0; m1 = mn1;

            float ls0 = 0.f, ls1 = 0.f;
#pragma unroll
            for (int j = 0; j < 8; j++) {
                s[j][0] = __expf(s[j][0] - mn0);
                s[j][1] = __expf(s[j][1] - mn0);
                s[j][2] = __expf(s[j][2] - mn1);
                s[j][3] = __expf(s[j][3] - mn1);
                ls0 += s[j][0] + s[j][1];
                ls1 += s[j][2] + s[j][3];
            }
            l0 = l0 * corr0 + ls0;
            l1 = l1 * corr1 + ls1;
#pragma unroll
            for (int j = 0; j < 8; j++) {
                o[j][0] *= corr0; o[j][1] *= corr0;
                o[j][2] *= corr1; o[j][3] *= corr1;
            }

#pragma unroll
            for (int kk = 0; kk < 4; kk++) {
                uint32_t a0 = pack_half2(s[2*kk][0],   s[2*kk][1]);
                uint32_t a1 = pack_half2(s[2*kk][2],   s[2*kk][3]);
                uint32_t a2 = pack_half2(s[2*kk+1][0], s[2*kk+1][1]);
                uint32_t a3 = pack_half2(s[2*kk+1][2], s[2*kk+1][3]);
#pragma unroll
                for (int jj = 0; jj < 4; jj++) {
                    uint32_t addr = sVs + (uint32_t)buf * (ABK * VSTR * 2)
                        + (uint32_t)((kk * 16 + (lane & 15)) * VSTR
                                     + jj * 16 + (lane >> 4) * 8) * 2;
                    uint32_t v0, v1, v2, v3;
                    asm volatile(
                        "ldmatrix.sync.aligned.m8n8.x4.trans.shared.b16 {%0,%1,%2,%3}, [%4];"
                        : "=r"(v0), "=r"(v1), "=r"(v2), "=r"(v3) : "r"(addr));
                    asm volatile(
                        "mma.sync.aligned.m16n8k16.row.col.f32.f16.f16.f32 "
                        "{%0,%1,%2,%3}, {%4,%5,%6,%7}, {%8,%9}, {%0,%1,%2,%3};"
                        : "+f"(o[2*jj][0]), "+f"(o[2*jj][1]), "+f"(o[2*jj][2]), "+f"(o[2*jj][3])
                        : "r"(a0), "r"(a1), "r"(a2), "r"(a3), "r"(v0), "r"(v1));
                    asm volatile(
                        "mma.sync.aligned.m16n8k16.row.col.f32.f16.f16.f32 "
                        "{%0,%1,%2,%3}, {%4,%5,%6,%7}, {%8,%9}, {%0,%1,%2,%3};"
                        : "+f"(o[2*jj+1][0]), "+f"(o[2*jj+1][1]), "+f"(o[2*jj+1][2]), "+f"(o[2*jj+1][3])
                        : "r"(a0), "r"(a1), "r"(a2), "r"(a3), "r"(v2), "r"(v3));
                }
            }
        }
        __syncthreads();
        buf ^= 1;
    }

    l0 += __shfl_xor_sync(0xffffffffu, l0, 1);
    l0 += __shfl_xor_sync(0xffffffffu, l0, 2);
    l1 += __shfl_xor_sync(0xffffffffu, l1, 1);
    l1 += __shfl_xor_sync(0xffffffffu, l1, 2);
    const float inv0 = 1.f / l0, inv1 = 1.f / l1;

    __half* o0p = OH + ((size_t)(b * Ss) + wq0 + r) * Dd + h * HD;
    __half* o1p = o0p + 8 * (size_t)Dd;
#pragma unroll
    for (int j = 0; j < 8; j++) {
        int col = j * 8 + 2 * c;
        *(__half2*)&o0p[col] = __floats2half2_rn(o[j][0] * inv0, o[j][1] * inv0);
        *(__half2*)&o1p[col] = __floats2half2_rn(o[j][2] * inv1, o[j][3] * inv1);
    }
}

// ---------------------------------------------------------------------------
// Launch
// ---------------------------------------------------------------------------
extern "C" void kernel_launch(void* const* d_in, const int* in_sizes, int n_in,
                              void* d_out, int out_size)
{
    const float* x       = (const float*)d_in[0];
    const float* Wq      = (const float*)d_in[1];
    const float* Wk      = (const float*)d_in[2];
    const float* Wv      = (const float*)d_in[3];
    const float* Wq_ded  = (const float*)d_in[4];
    const float* Wk_ded  = (const float*)d_in[5];
    const float* Wv_ded  = (const float*)d_in[6];
    const float* Wo      = (const float*)d_in[7];

    float* out_o = (float*)d_out;
    float* out_k = out_o + ELEM;
    float* out_v = out_k + ELEM;

    __half *xh = nullptr, *wth = nullptr, *ah = nullptr;
    __half *qh = nullptr, *kh = nullptr, *vh = nullptr;
    cudaGetSymbolAddress((void**)&xh,   g_xh);
    cudaGetSymbolAddress((void**)&wth,  g_wth);
    cudaGetSymbolAddress((void**)&ah,   g_ah);
    cudaGetSymbolAddress((void**)&qh,   g_qh);
    cudaGetSymbolAddress((void**)&kh,   g_kh);
    cudaGetSymbolAddress((void**)&vh,   g_vh);
    __half* wtq = wth;
    __half* wtk = wth + (size_t)Dd * Dd;
    __half* wtv = wth + 2 * (size_t)Dd * Dd;
    __half* wto = wth + 3 * (size_t)Dd * Dd;

    cudaFuncSetAttribute(fused_qkv_ded_kernel,
                         cudaFuncAttributeMaxDynamicSharedMemorySize, GEMM_SMEM);
    cudaFuncSetAttribute(h_gemm_kernel,
                         cudaFuncAttributeMaxDynamicSharedMemorySize, GEMM_SMEM);
    cudaFuncSetAttribute(attn_tc_kernel,
                         cudaFuncAttributeMaxDynamicSharedMemorySize, ATTN_SMEM);

    // 0) x -> fp16; batched transpose+convert of the 4 weight matrices
    cvt_half_kernel<<<2048, 256>>>(x, xh, (int)(ELEM / 4));
    dim3 tg(32, 32, 4), tb(32, 8);
    transpose_h4_kernel<<<tg, tb>>>(Wq, Wk, Wv, Wo, wth);

    // 1) fused QKV GEMM + dedicated projection (striped 1D grid, overlap
    //    DRAM-bound ded blocks with tensor-bound GEMM blocks)
    fused_qkv_ded_kernel<<<2304, 256, GEMM_SMEM>>>(
        xh, wtq, wtk, wtv,
        x, Wq_ded, Wk_ded, Wv_ded,
        out_k, out_v, qh, kh, vh);

    // 2) fully-fp16 tensor-core causal attention
    dim3 ag(Ss / ABQ, Hh, Bb);
    attn_tc_kernel<<<ag, 256, ATTN_SMEM>>>(qh, kh, vh, ah);

    // 3) output projection
    dim3 gg1(Dd / GBN, TOK / GBM);
    h_gemm_kernel<<<gg1, 256, GEMM_SMEM>>>(ah, wto, out_o);
}